// round 4
// baseline (speedup 1.0000x reference)
#include <cuda_runtime.h>
#include <math.h>

#define NND 50000
#define NED 800000
#define D   64

// ---- scratch (allocation-free device globals) ----
__device__ __align__(16) int   g_degout[NND];
__device__ __align__(16) int   g_degin[NND];
__device__ float g_outn[NND];
__device__ float g_inn[NND];
__device__ int   g_rowstart[NND];
__device__ int   g_cursor[NND];
__device__ int   g_esrc[NED];      // edge src ids grouped by dst
__device__ float g_y[NND * D];     // (feat @ W1) * outn
__device__ float g_z[NND];         // outn * dot(relu-layer output, W2)
__device__ int   g_total;

// ---------------------------------------------------------------- init (vectorized zero)
__global__ void k_init(int nN) {
    int i = blockIdx.x * blockDim.x + threadIdx.x;
    int n4 = nN >> 2;
    int4 z = make_int4(0, 0, 0, 0);
    if (i < n4) {
        reinterpret_cast<int4*>(g_degout)[i] = z;
        reinterpret_cast<int4*>(g_degin)[i] = z;
    }
    if (i == 0) {
        g_total = 0;
        for (int r = nN & ~3; r < nN; r++) { g_degout[r] = 0; g_degin[r] = 0; }
    }
}

// ---------------------------------------------------------------- degrees (4 edges/thread, RED no-return)
__global__ void k_deg(const int* __restrict__ src, const int* __restrict__ dst, int nE) {
    int t = blockIdx.x * blockDim.x + threadIdx.x;
    int base = t * 4;
    if (base + 3 < nE) {
        int4 s = reinterpret_cast<const int4*>(src)[t];
        int4 d = reinterpret_cast<const int4*>(dst)[t];
        atomicAdd(&g_degout[s.x], 1); atomicAdd(&g_degout[s.y], 1);
        atomicAdd(&g_degout[s.z], 1); atomicAdd(&g_degout[s.w], 1);
        atomicAdd(&g_degin[d.x], 1);  atomicAdd(&g_degin[d.y], 1);
        atomicAdd(&g_degin[d.z], 1);  atomicAdd(&g_degin[d.w], 1);
    } else {
        for (int e = base; e < nE; e++) {
            atomicAdd(&g_degout[src[e]], 1);
            atomicAdd(&g_degin[dst[e]], 1);
        }
    }
}

// ---------------------------------------------------------------- norms + row offsets (atomic chunk grab)
__global__ void k_norm(int nN) {
    int i = blockIdx.x * blockDim.x + threadIdx.x;
    if (i < nN) {
        int din = g_degin[i];
        int rs = atomicAdd(&g_total, din);
        g_rowstart[i] = rs;
        g_cursor[i]   = rs;
        g_outn[i] = rsqrtf(fmaxf((float)g_degout[i], 1.f));
        g_inn[i]  = rsqrtf(fmaxf((float)din, 1.f));
    }
}

// ---------------------------------------------------------------- fused: CSR fill + GEMM (role-split blocks)
// blocks [0, nCsr):   CSR fill, 4 edges/thread
// blocks [nCsr, ...): y = (feat @ W1) * outn, grid-stride warp per node
__global__ void k_csr_gemm(const int* __restrict__ src, const int* __restrict__ dst, int nE,
                           const float* __restrict__ feat, const float* __restrict__ W1,
                           int nN, int nCsr, int nGemmBlocks) {
    if (blockIdx.x < nCsr) {
        int t = blockIdx.x * blockDim.x + threadIdx.x;
        int base = t * 4;
        if (base + 3 < nE) {
            int4 s = reinterpret_cast<const int4*>(src)[t];
            int4 d = reinterpret_cast<const int4*>(dst)[t];
            int p0 = atomicAdd(&g_cursor[d.x], 1);
            int p1 = atomicAdd(&g_cursor[d.y], 1);
            int p2 = atomicAdd(&g_cursor[d.z], 1);
            int p3 = atomicAdd(&g_cursor[d.w], 1);
            g_esrc[p0] = s.x; g_esrc[p1] = s.y; g_esrc[p2] = s.z; g_esrc[p3] = s.w;
        } else {
            for (int e = base; e < nE; e++) {
                int pos = atomicAdd(&g_cursor[dst[e]], 1);
                g_esrc[pos] = src[e];
            }
        }
        return;
    }
    // ---- GEMM role ----
    __shared__ float2 Ws[D * 32];   // Ws[k*32+l] = (W1[k][2l], W1[k][2l+1])
    int t = threadIdx.x;
    for (int i = t; i < D * 32; i += blockDim.x)
        Ws[i] = reinterpret_cast<const float2*>(W1)[i];
    __syncthreads();

    int lane = t & 31;
    int wid  = t >> 5;
    int wpb  = blockDim.x >> 5;
    int warps = wpb * nGemmBlocks;
    int bi = blockIdx.x - nCsr;
    for (int node = bi * wpb + wid; node < nN; node += warps) {
        float x0 = feat[node * D + lane];
        float x1 = feat[node * D + 32 + lane];
        float ax = 0.f, ay = 0.f;
#pragma unroll
        for (int k = 0; k < D; k++) {
            float v = __shfl_sync(0xffffffffu, (k < 32) ? x0 : x1, k & 31);
            float2 w = Ws[k * 32 + lane];
            ax = fmaf(v, w.x, ax);
            ay = fmaf(v, w.y, ay);
        }
        float on = g_outn[node];
        float2 r; r.x = ax * on; r.y = ay * on;
        reinterpret_cast<float2*>(g_y)[node * 32 + lane] = r;
    }
}

// ---------------------------------------------------------------- layer 1 pull + epilogue -> z
// z[node] = outn * dot( relu(inn * sum_src y[src] + b1), W2 );  warp per node, 4-way ILP
__global__ void k_pull1(const float* __restrict__ b1, const float* __restrict__ W2, int nN) {
    int t = threadIdx.x;
    int lane = t & 31;
    int wid  = t >> 5;
    int wpb  = blockDim.x >> 5;
    int warps = wpb * gridDim.x;
    float2 b1v = reinterpret_cast<const float2*>(b1)[lane];
    float2 w2v = reinterpret_cast<const float2*>(W2)[lane];
    const float2* y2 = reinterpret_cast<const float2*>(g_y);

    for (int node = blockIdx.x * wpb + wid; node < nN; node += warps) {
        int row = g_rowstart[node];
        int deg = g_degin[node];
        float ax0 = 0.f, ay0 = 0.f, ax1 = 0.f, ay1 = 0.f;
        float ax2 = 0.f, ay2 = 0.f, ax3 = 0.f, ay3 = 0.f;
        for (int base = 0; base < deg; base += 32) {
            int n = min(32, deg - base);
            int eid = (lane < n) ? g_esrc[row + base + lane] : 0;
            int j = 0;
            for (; j + 4 <= n; j += 4) {
                int s0 = __shfl_sync(0xffffffffu, eid, j);
                int s1 = __shfl_sync(0xffffffffu, eid, j + 1);
                int s2 = __shfl_sync(0xffffffffu, eid, j + 2);
                int s3 = __shfl_sync(0xffffffffu, eid, j + 3);
                float2 v0 = y2[s0 * 32 + lane];
                float2 v1 = y2[s1 * 32 + lane];
                float2 v2 = y2[s2 * 32 + lane];
                float2 v3 = y2[s3 * 32 + lane];
                ax0 += v0.x; ay0 += v0.y;
                ax1 += v1.x; ay1 += v1.y;
                ax2 += v2.x; ay2 += v2.y;
                ax3 += v3.x; ay3 += v3.y;
            }
            for (; j < n; j++) {
                int s = __shfl_sync(0xffffffffu, eid, j);
                float2 v = y2[s * 32 + lane];
                ax0 += v.x; ay0 += v.y;
            }
        }
        float ax = (ax0 + ax1) + (ax2 + ax3);
        float ay = (ay0 + ay1) + (ay2 + ay3);
        float inn = g_inn[node];
        float hx = fmaxf(fmaf(ax, inn, b1v.x), 0.f);
        float hy = fmaxf(fmaf(ay, inn, b1v.y), 0.f);
        float p = hx * w2v.x + hy * w2v.y;
#pragma unroll
        for (int o = 16; o; o >>= 1) p += __shfl_xor_sync(0xffffffffu, p, o);
        if (lane == 0) g_z[node] = p * g_outn[node];
    }
}

// ---------------------------------------------------------------- layer 2: scalar pull + sigmoid (4-way ILP)
__global__ void k_pull2(const float* __restrict__ b2, float* __restrict__ out, int nN) {
    int i = blockIdx.x * blockDim.x + threadIdx.x;
    if (i >= nN) return;
    int row = g_rowstart[i];
    int deg = g_degin[i];
    float s0 = 0.f, s1 = 0.f, s2 = 0.f, s3 = 0.f;
    int e = 0;
    for (; e + 4 <= deg; e += 4) {
        s0 += g_z[g_esrc[row + e]];
        s1 += g_z[g_esrc[row + e + 1]];
        s2 += g_z[g_esrc[row + e + 2]];
        s3 += g_z[g_esrc[row + e + 3]];
    }
    for (; e < deg; e++) s0 += g_z[g_esrc[row + e]];
    float s = (s0 + s1) + (s2 + s3);
    out[i] = 1.f / (1.f + expf(-(s * g_inn[i] + b2[0])));
}

// ---------------------------------------------------------------- launch
extern "C" void kernel_launch(void* const* d_in, const int* in_sizes, int n_in,
                              void* d_out, int out_size) {
    const float* feat = (const float*)d_in[0];
    const float* W1   = (const float*)d_in[1];
    const float* b1   = (const float*)d_in[2];
    const float* W2   = (const float*)d_in[3];
    const float* b2   = (const float*)d_in[4];
    const int*   src  = (const int*)d_in[5];
    const int*   dst  = (const int*)d_in[6];
    float* out = (float*)d_out;

    int nN = in_sizes[0] / D;
    int nE = in_sizes[5];

    const int B = 256;
    int gNode  = (nN + B - 1) / B;
    int gDeg   = (nE + B * 4 - 1) / (B * 4);
    int gCsr   = gDeg;
    int gGemm  = 592;                  // grid-stride: 4 blocks/SM
    int gPull1 = 1184;                 // grid-stride: 8 blocks/SM

    k_init    <<<gNode, B>>>(nN);
    k_deg     <<<gDeg,  B>>>(src, dst, nE);
    k_norm    <<<gNode, B>>>(nN);
    k_csr_gemm<<<gCsr + gGemm, B>>>(src, dst, nE, feat, W1, nN, gCsr, gGemm);
    k_pull1   <<<gPull1, B>>>(b1, W2, nN);
    k_pull2   <<<gNode, B>>>(b2, out, nN);
}

// round 5
// speedup vs baseline: 1.0394x; 1.0394x over previous
#include <cuda_runtime.h>
#include <math.h>

#define NND 50000
#define NED 800000
#define D   64

// ---- scratch (allocation-free device globals) ----
__device__ __align__(16) int   g_degout[NND];
__device__ __align__(16) int   g_degin[NND];
__device__ float g_outn[NND];
__device__ float g_inn[NND];
__device__ int   g_rowstart[NND];
__device__ int   g_cursor[NND];
__device__ int   g_esrc[NED];      // edge src ids grouped by dst
__device__ float g_y[NND * D];     // (feat @ W1) * outn
__device__ float g_z[NND];         // outn * dot(relu-layer output, W2)
__device__ int   g_total;

// ---------------------------------------------------------------- init (vectorized zero)
__global__ void k_init(int nN) {
    int i = blockIdx.x * blockDim.x + threadIdx.x;
    int n4 = nN >> 2;
    int4 z = make_int4(0, 0, 0, 0);
    if (i < n4) {
        reinterpret_cast<int4*>(g_degout)[i] = z;
        reinterpret_cast<int4*>(g_degin)[i] = z;
    }
    if (i == 0) {
        g_total = 0;
        for (int r = nN & ~3; r < nN; r++) { g_degout[r] = 0; g_degin[r] = 0; }
    }
}

// ---------------------------------------------------------------- degrees (4 edges/thread)
__global__ void k_deg(const int* __restrict__ src, const int* __restrict__ dst, int nE) {
    int t = blockIdx.x * blockDim.x + threadIdx.x;
    int base = t * 4;
    if (base + 3 < nE) {
        int4 s = reinterpret_cast<const int4*>(src)[t];
        int4 d = reinterpret_cast<const int4*>(dst)[t];
        atomicAdd(&g_degout[s.x], 1); atomicAdd(&g_degout[s.y], 1);
        atomicAdd(&g_degout[s.z], 1); atomicAdd(&g_degout[s.w], 1);
        atomicAdd(&g_degin[d.x], 1);  atomicAdd(&g_degin[d.y], 1);
        atomicAdd(&g_degin[d.z], 1);  atomicAdd(&g_degin[d.w], 1);
    } else {
        for (int e = base; e < nE; e++) {
            atomicAdd(&g_degout[src[e]], 1);
            atomicAdd(&g_degin[dst[e]], 1);
        }
    }
}

// ---------------------------------------------------------------- norms + row offsets (atomic chunk grab)
__global__ void k_norm(int nN) {
    int i = blockIdx.x * blockDim.x + threadIdx.x;
    if (i < nN) {
        int din = g_degin[i];
        int rs = atomicAdd(&g_total, din);
        g_rowstart[i] = rs;
        g_cursor[i]   = rs;
        g_outn[i] = rsqrtf(fmaxf((float)g_degout[i], 1.f));
        g_inn[i]  = rsqrtf(fmaxf((float)din, 1.f));
    }
}

// ---------------------------------------------------------------- CSR fill (4 edges/thread)
__global__ void k_csr(const int* __restrict__ src, const int* __restrict__ dst, int nE) {
    int t = blockIdx.x * blockDim.x + threadIdx.x;
    int base = t * 4;
    if (base + 3 < nE) {
        int4 s = reinterpret_cast<const int4*>(src)[t];
        int4 d = reinterpret_cast<const int4*>(dst)[t];
        int p0 = atomicAdd(&g_cursor[d.x], 1);
        int p1 = atomicAdd(&g_cursor[d.y], 1);
        int p2 = atomicAdd(&g_cursor[d.z], 1);
        int p3 = atomicAdd(&g_cursor[d.w], 1);
        g_esrc[p0] = s.x; g_esrc[p1] = s.y; g_esrc[p2] = s.z; g_esrc[p3] = s.w;
    } else {
        for (int e = base; e < nE; e++) {
            int pos = atomicAdd(&g_cursor[dst[e]], 1);
            g_esrc[pos] = src[e];
        }
    }
}

// ---------------------------------------------------------------- y = (feat @ W1) * outn (grid-stride warp/node)
__global__ void k_gemm(const float* __restrict__ feat, const float* __restrict__ W1, int nN) {
    __shared__ float2 Ws[D * 32];   // Ws[k*32+l] = (W1[k][2l], W1[k][2l+1])
    int t = threadIdx.x;
    for (int i = t; i < D * 32; i += blockDim.x)
        Ws[i] = reinterpret_cast<const float2*>(W1)[i];
    __syncthreads();

    int lane = t & 31;
    int wid  = t >> 5;
    int wpb  = blockDim.x >> 5;
    int warps = wpb * gridDim.x;
    for (int node = blockIdx.x * wpb + wid; node < nN; node += warps) {
        float x0 = feat[node * D + lane];
        float x1 = feat[node * D + 32 + lane];
        float ax = 0.f, ay = 0.f;
#pragma unroll
        for (int k = 0; k < D; k++) {
            float v = __shfl_sync(0xffffffffu, (k < 32) ? x0 : x1, k & 31);
            float2 w = Ws[k * 32 + lane];
            ax = fmaf(v, w.x, ax);
            ay = fmaf(v, w.y, ay);
        }
        float on = g_outn[node];
        float2 r; r.x = ax * on; r.y = ay * on;
        reinterpret_cast<float2*>(g_y)[node * 32 + lane] = r;
    }
}

// ---------------------------------------------------------------- layer 1 pull + epilogue -> z
// z[node] = outn * dot( relu(inn * sum_src y[src] + b1), W2 );  warp per node, 4-way ILP
__global__ void k_pull1(const float* __restrict__ b1, const float* __restrict__ W2, int nN) {
    int t = threadIdx.x;
    int lane = t & 31;
    int wid  = t >> 5;
    int wpb  = blockDim.x >> 5;
    int warps = wpb * gridDim.x;
    float2 b1v = reinterpret_cast<const float2*>(b1)[lane];
    float2 w2v = reinterpret_cast<const float2*>(W2)[lane];
    const float2* y2 = reinterpret_cast<const float2*>(g_y);

    for (int node = blockIdx.x * wpb + wid; node < nN; node += warps) {
        int row = g_rowstart[node];
        int deg = g_degin[node];
        float ax0 = 0.f, ay0 = 0.f, ax1 = 0.f, ay1 = 0.f;
        float ax2 = 0.f, ay2 = 0.f, ax3 = 0.f, ay3 = 0.f;
        for (int base = 0; base < deg; base += 32) {
            int n = min(32, deg - base);
            int eid = (lane < n) ? g_esrc[row + base + lane] : 0;
            int j = 0;
            for (; j + 4 <= n; j += 4) {
                int s0 = __shfl_sync(0xffffffffu, eid, j);
                int s1 = __shfl_sync(0xffffffffu, eid, j + 1);
                int s2 = __shfl_sync(0xffffffffu, eid, j + 2);
                int s3 = __shfl_sync(0xffffffffu, eid, j + 3);
                float2 v0 = y2[s0 * 32 + lane];
                float2 v1 = y2[s1 * 32 + lane];
                float2 v2 = y2[s2 * 32 + lane];
                float2 v3 = y2[s3 * 32 + lane];
                ax0 += v0.x; ay0 += v0.y;
                ax1 += v1.x; ay1 += v1.y;
                ax2 += v2.x; ay2 += v2.y;
                ax3 += v3.x; ay3 += v3.y;
            }
            for (; j < n; j++) {
                int s = __shfl_sync(0xffffffffu, eid, j);
                float2 v = y2[s * 32 + lane];
                ax0 += v.x; ay0 += v.y;
            }
        }
        float ax = (ax0 + ax1) + (ax2 + ax3);
        float ay = (ay0 + ay1) + (ay2 + ay3);
        float inn = g_inn[node];
        float hx = fmaxf(fmaf(ax, inn, b1v.x), 0.f);
        float hy = fmaxf(fmaf(ay, inn, b1v.y), 0.f);
        float p = hx * w2v.x + hy * w2v.y;
#pragma unroll
        for (int o = 16; o; o >>= 1) p += __shfl_xor_sync(0xffffffffu, p, o);
        if (lane == 0) g_z[node] = p * g_outn[node];
    }
}

// ---------------------------------------------------------------- layer 2: scalar pull + sigmoid (4-way ILP)
__global__ void k_pull2(const float* __restrict__ b2, float* __restrict__ out, int nN) {
    int i = blockIdx.x * blockDim.x + threadIdx.x;
    if (i >= nN) return;
    int row = g_rowstart[i];
    int deg = g_degin[i];
    float s0 = 0.f, s1 = 0.f, s2 = 0.f, s3 = 0.f;
    int e = 0;
    for (; e + 4 <= deg; e += 4) {
        s0 += g_z[g_esrc[row + e]];
        s1 += g_z[g_esrc[row + e + 1]];
        s2 += g_z[g_esrc[row + e + 2]];
        s3 += g_z[g_esrc[row + e + 3]];
    }
    for (; e < deg; e++) s0 += g_z[g_esrc[row + e]];
    float s = (s0 + s1) + (s2 + s3);
    out[i] = 1.f / (1.f + expf(-(s * g_inn[i] + b2[0])));
}

// ---------------------------------------------------------------- launch
extern "C" void kernel_launch(void* const* d_in, const int* in_sizes, int n_in,
                              void* d_out, int out_size) {
    const float* feat = (const float*)d_in[0];
    const float* W1   = (const float*)d_in[1];
    const float* b1   = (const float*)d_in[2];
    const float* W2   = (const float*)d_in[3];
    const float* b2   = (const float*)d_in[4];
    const int*   src  = (const int*)d_in[5];
    const int*   dst  = (const int*)d_in[6];
    float* out = (float*)d_out;

    int nN = in_sizes[0] / D;
    int nE = in_sizes[5];

    const int B = 256;
    int gNode  = (nN + B - 1) / B;
    int gEdge4 = (nE + B * 4 - 1) / (B * 4);
    int gGemm  = 592;                  // grid-stride: 4 blocks/SM
    int gPull1 = 1184;                 // grid-stride: 8 blocks/SM

    k_init <<<gNode, B>>>(nN);
    k_deg  <<<gEdge4, B>>>(src, dst, nE);
    k_norm <<<gNode, B>>>(nN);
    k_csr  <<<gEdge4, B>>>(src, dst, nE);
    k_gemm <<<gGemm, B>>>(feat, W1, nN);
    k_pull1<<<gPull1, B>>>(b1, W2, nN);
    k_pull2<<<gNode, B>>>(b2, out, nN);
}

// round 6
// speedup vs baseline: 1.1377x; 1.0945x over previous
#include <cuda_runtime.h>
#include <math.h>

#define NND 50000
#define NED 800000
#define D   64

// ---- scratch (allocation-free device globals) ----
__device__ int   g_degout[NND];
__device__ int   g_degin[NND];
__device__ float g_outn[NND];
__device__ float g_inn[NND];
__device__ int   g_rowstart[NND];
__device__ int   g_cursor[NND];
__device__ int   g_esrc[NED];      // edge src ids grouped by dst
__device__ float g_y[NND * D];     // (feat @ W1) * outn
__device__ float g_z[NND];         // outn * dot(relu-layer output, W2)
__device__ float g_s[NND];         // layer-2 scatter accumulator (scalar)
__device__ int   g_total;

// ---------------------------------------------------------------- init
__global__ void k_init(int nN) {
    int i = blockIdx.x * blockDim.x + threadIdx.x;
    if (i < nN) { g_degout[i] = 0; g_degin[i] = 0; g_s[i] = 0.f; }
    if (i == 0) g_total = 0;
}

// ---------------------------------------------------------------- degrees
__global__ void k_deg(const int* __restrict__ src, const int* __restrict__ dst, int nE) {
    int e = blockIdx.x * blockDim.x + threadIdx.x;
    if (e < nE) {
        atomicAdd(&g_degout[src[e]], 1);
        atomicAdd(&g_degin[dst[e]], 1);
    }
}

// ---------------------------------------------------------------- norms + row offsets
// warp-aggregated chunk grab: 1 atomic per warp instead of 1 per node
__global__ void k_norm(int nN) {
    int i = blockIdx.x * blockDim.x + threadIdx.x;
    int lane = threadIdx.x & 31;
    int din = (i < nN) ? g_degin[i] : 0;

    // inclusive warp scan of din
    int scan = din;
#pragma unroll
    for (int off = 1; off < 32; off <<= 1) {
        int u = __shfl_up_sync(0xffffffffu, scan, off);
        if (lane >= off) scan += u;
    }
    int wsum = __shfl_sync(0xffffffffu, scan, 31);
    int base = 0;
    if (lane == 31) base = atomicAdd(&g_total, wsum);
    base = __shfl_sync(0xffffffffu, base, 31);

    if (i < nN) {
        int rs = base + scan - din;   // exclusive position within warp chunk
        g_rowstart[i] = rs;
        g_cursor[i]   = rs;
        g_outn[i] = rsqrtf(fmaxf((float)g_degout[i], 1.f));
        g_inn[i]  = rsqrtf(fmaxf((float)din, 1.f));
    }
}

// ---------------------------------------------------------------- CSR fill
__global__ void k_csr(const int* __restrict__ src, const int* __restrict__ dst, int nE) {
    int e = blockIdx.x * blockDim.x + threadIdx.x;
    if (e < nE) {
        int pos = atomicAdd(&g_cursor[dst[e]], 1);
        g_esrc[pos] = src[e];
    }
}

// ---------------------------------------------------------------- y = (feat @ W1) * outn   (warp per node)
__global__ void k_gemm(const float* __restrict__ feat, const float* __restrict__ W1, int nN) {
    __shared__ float2 Ws[D * 32];   // Ws[k*32+l] = (W1[k][2l], W1[k][2l+1])
    int t = threadIdx.x;
    for (int i = t; i < D * 32; i += blockDim.x)
        Ws[i] = reinterpret_cast<const float2*>(W1)[i];
    __syncthreads();

    int lane = t & 31;
    int wid  = t >> 5;
    int warps = (blockDim.x >> 5) * gridDim.x;
    for (int node = blockIdx.x * (blockDim.x >> 5) + wid; node < nN; node += warps) {
        float x0 = feat[node * D + lane];
        float x1 = feat[node * D + 32 + lane];
        float ax = 0.f, ay = 0.f;
#pragma unroll
        for (int k = 0; k < D; k++) {
            float v = __shfl_sync(0xffffffffu, (k < 32) ? x0 : x1, k & 31);
            float2 w = Ws[k * 32 + lane];
            ax = fmaf(v, w.x, ax);
            ay = fmaf(v, w.y, ay);
        }
        float on = g_outn[node];
        float2 r; r.x = ax * on; r.y = ay * on;
        reinterpret_cast<float2*>(g_y)[node * 32 + lane] = r;
    }
}

// ---------------------------------------------------------------- layer 1 pull + epilogue -> z
// z[node] = outn[node] * dot( relu(inn*Σ y[src] + b1), W2 )
__global__ void k_pull1(const float* __restrict__ b1, const float* __restrict__ W2, int nN) {
    int t = threadIdx.x;
    int lane = t & 31;
    int wid  = t >> 5;
    int warps = (blockDim.x >> 5) * gridDim.x;
    float2 b1v = reinterpret_cast<const float2*>(b1)[lane];
    float2 w2v = reinterpret_cast<const float2*>(W2)[lane];
    const float2* y2 = reinterpret_cast<const float2*>(g_y);

    for (int node = blockIdx.x * (blockDim.x >> 5) + wid; node < nN; node += warps) {
        int row = g_rowstart[node];
        int deg = g_degin[node];
        float ax = 0.f, ay = 0.f;
        for (int base = 0; base < deg; base += 32) {
            int n = min(32, deg - base);
            int eid = (lane < n) ? g_esrc[row + base + lane] : 0;
            for (int j = 0; j < n; j++) {
                int s = __shfl_sync(0xffffffffu, eid, j);
                float2 v = y2[s * 32 + lane];
                ax += v.x;
                ay += v.y;
            }
        }
        float inn = g_inn[node];
        float hx = fmaxf(fmaf(ax, inn, b1v.x), 0.f);
        float hy = fmaxf(fmaf(ay, inn, b1v.y), 0.f);
        float p = hx * w2v.x + hy * w2v.y;
#pragma unroll
        for (int o = 16; o; o >>= 1) p += __shfl_xor_sync(0xffffffffu, p, o);
        if (lane == 0) g_z[node] = p * g_outn[node];
    }
}

// ---------------------------------------------------------------- layer 2 scatter: s[dst] += z[src]
__global__ void k_scatter2(const int* __restrict__ src, const int* __restrict__ dst, int nE) {
    int e = blockIdx.x * blockDim.x + threadIdx.x;
    if (e < nE) {
        float v = g_z[src[e]];
        atomicAdd(&g_s[dst[e]], v);   // compiles to REDG (no return use)
    }
}

// ---------------------------------------------------------------- output: sigmoid(s*inn + b2)
__global__ void k_out(const float* __restrict__ b2, float* __restrict__ out, int nN) {
    int i = blockIdx.x * blockDim.x + threadIdx.x;
    if (i < nN) {
        out[i] = 1.f / (1.f + expf(-(g_s[i] * g_inn[i] + b2[0])));
    }
}

// ---------------------------------------------------------------- launch
extern "C" void kernel_launch(void* const* d_in, const int* in_sizes, int n_in,
                              void* d_out, int out_size) {
    const float* feat = (const float*)d_in[0];
    const float* W1   = (const float*)d_in[1];
    const float* b1   = (const float*)d_in[2];
    const float* W2   = (const float*)d_in[3];
    const float* b2   = (const float*)d_in[4];
    const int*   src  = (const int*)d_in[5];
    const int*   dst  = (const int*)d_in[6];
    float* out = (float*)d_out;

    int nN = in_sizes[0] / D;
    int nE = in_sizes[5];

    const int B = 256;
    int gNode = (nN + B - 1) / B;
    int gEdge = (nE + B - 1) / B;
    int gWarp = (nN + (B / 32) - 1) / (B / 32);

    k_init    <<<gNode, B>>>(nN);
    k_deg     <<<gEdge, B>>>(src, dst, nE);
    k_norm    <<<gNode, B>>>(nN);
    k_csr     <<<gEdge, B>>>(src, dst, nE);
    k_gemm    <<<gWarp, B>>>(feat, W1, nN);
    k_pull1   <<<gWarp, B>>>(b1, W2, nN);
    k_scatter2<<<gEdge, B>>>(src, dst, nE);
    k_out     <<<gNode, B>>>(b2, out, nN);
}

// round 7
// speedup vs baseline: 1.3267x; 1.1661x over previous
#include <cuda_runtime.h>
#include <math.h>

#define NND 50000
#define NED 800000
#define D   64

// ---- scratch (allocation-free device globals) ----
__device__ int   g_degout[NND];
__device__ int   g_degin[NND];
__device__ float g_outn[NND];
__device__ float g_inn[NND];
__device__ int   g_rowstart[NND];
__device__ int   g_cursor[NND];
__device__ int   g_esrc[NED];      // edge src ids grouped by dst
__device__ float g_y[NND * D];     // (feat @ W1) * outn
__device__ float g_z[NND];         // outn * dot(relu-layer output, W2)
__device__ int   g_total;

// ---------------------------------------------------------------- init
__global__ void k_init(int nN) {
    int i = blockIdx.x * blockDim.x + threadIdx.x;
    if (i < nN) { g_degout[i] = 0; g_degin[i] = 0; }
    if (i == 0) g_total = 0;
}

// ---------------------------------------------------------------- degrees
__global__ void k_deg(const int* __restrict__ src, const int* __restrict__ dst, int nE) {
    int e = blockIdx.x * blockDim.x + threadIdx.x;
    if (e < nE) {
        atomicAdd(&g_degout[src[e]], 1);
        atomicAdd(&g_degin[dst[e]], 1);
    }
}

// ---------------------------------------------------------------- norms + row offsets (warp-agg chunk grab)
__global__ void k_norm(int nN) {
    int i = blockIdx.x * blockDim.x + threadIdx.x;
    int lane = threadIdx.x & 31;
    int din = (i < nN) ? g_degin[i] : 0;

    int scan = din;
#pragma unroll
    for (int off = 1; off < 32; off <<= 1) {
        int u = __shfl_up_sync(0xffffffffu, scan, off);
        if (lane >= off) scan += u;
    }
    int wsum = __shfl_sync(0xffffffffu, scan, 31);
    int base = 0;
    if (lane == 31) base = atomicAdd(&g_total, wsum);
    base = __shfl_sync(0xffffffffu, base, 31);

    if (i < nN) {
        int rs = base + scan - din;
        g_rowstart[i] = rs;
        g_cursor[i]   = rs;
        g_outn[i] = rsqrtf(fmaxf((float)g_degout[i], 1.f));
        g_inn[i]  = rsqrtf(fmaxf((float)din, 1.f));
    }
}

// ---------------------------------------------------------------- CSR fill
__global__ void k_csr(const int* __restrict__ src, const int* __restrict__ dst, int nE) {
    int e = blockIdx.x * blockDim.x + threadIdx.x;
    if (e < nE) {
        int pos = atomicAdd(&g_cursor[dst[e]], 1);
        g_esrc[pos] = src[e];
    }
}

// ---------------------------------------------------------------- y = (feat @ W1) * outn (grid-stride warp/node)
__global__ void k_gemm(const float* __restrict__ feat, const float* __restrict__ W1, int nN) {
    __shared__ float2 Ws[D * 32];   // Ws[k*32+l] = (W1[k][2l], W1[k][2l+1])
    int t = threadIdx.x;
    for (int i = t; i < D * 32; i += blockDim.x)
        Ws[i] = reinterpret_cast<const float2*>(W1)[i];
    __syncthreads();

    int lane = t & 31;
    int wid  = t >> 5;
    int wpb  = blockDim.x >> 5;
    int warps = wpb * gridDim.x;
    for (int node = blockIdx.x * wpb + wid; node < nN; node += warps) {
        float x0 = feat[node * D + lane];
        float x1 = feat[node * D + 32 + lane];
        float ax = 0.f, ay = 0.f;
#pragma unroll
        for (int k = 0; k < D; k++) {
            float v = __shfl_sync(0xffffffffu, (k < 32) ? x0 : x1, k & 31);
            float2 w = Ws[k * 32 + lane];
            ax = fmaf(v, w.x, ax);
            ay = fmaf(v, w.y, ay);
        }
        float on = g_outn[node];
        float2 r; r.x = ax * on; r.y = ay * on;
        reinterpret_cast<float2*>(g_y)[node * 32 + lane] = r;
    }
}

// ---------------------------------------------------------------- layer 1 pull + epilogue -> z  (R3 exact)
__global__ void k_pull1(const float* __restrict__ b1, const float* __restrict__ W2, int nN) {
    int t = threadIdx.x;
    int lane = t & 31;
    int wid  = t >> 5;
    int warps = (blockDim.x >> 5) * gridDim.x;
    float2 b1v = reinterpret_cast<const float2*>(b1)[lane];
    float2 w2v = reinterpret_cast<const float2*>(W2)[lane];
    const float2* y2 = reinterpret_cast<const float2*>(g_y);

    for (int node = blockIdx.x * (blockDim.x >> 5) + wid; node < nN; node += warps) {
        int row = g_rowstart[node];
        int deg = g_degin[node];
        float ax = 0.f, ay = 0.f;
        for (int base = 0; base < deg; base += 32) {
            int n = min(32, deg - base);
            int eid = (lane < n) ? g_esrc[row + base + lane] : 0;
            for (int j = 0; j < n; j++) {
                int s = __shfl_sync(0xffffffffu, eid, j);
                float2 v = y2[s * 32 + lane];
                ax += v.x;
                ay += v.y;
            }
        }
        float inn = g_inn[node];
        float hx = fmaxf(fmaf(ax, inn, b1v.x), 0.f);
        float hy = fmaxf(fmaf(ay, inn, b1v.y), 0.f);
        float p = hx * w2v.x + hy * w2v.y;
#pragma unroll
        for (int o = 16; o; o >>= 1) p += __shfl_xor_sync(0xffffffffu, p, o);
        if (lane == 0) g_z[node] = p * g_outn[node];
    }
}

// ---------------------------------------------------------------- layer 2: scalar pull + sigmoid (R3 exact)
__global__ void k_pull2(const float* __restrict__ b2, float* __restrict__ out, int nN) {
    int i = blockIdx.x * blockDim.x + threadIdx.x;
    if (i < nN) {
        int row = g_rowstart[i];
        int deg = g_degin[i];
        float s = 0.f;
        for (int e = 0; e < deg; e++) s += g_z[g_esrc[row + e]];
        out[i] = 1.f / (1.f + expf(-(s * g_inn[i] + b2[0])));
    }
}

// ---------------------------------------------------------------- launch
extern "C" void kernel_launch(void* const* d_in, const int* in_sizes, int n_in,
                              void* d_out, int out_size) {
    const float* feat = (const float*)d_in[0];
    const float* W1   = (const float*)d_in[1];
    const float* b1   = (const float*)d_in[2];
    const float* W2   = (const float*)d_in[3];
    const float* b2   = (const float*)d_in[4];
    const int*   src  = (const int*)d_in[5];
    const int*   dst  = (const int*)d_in[6];
    float* out = (float*)d_out;

    int nN = in_sizes[0] / D;
    int nE = in_sizes[5];

    // One-time handles (created on the first, non-captured, call; only
    // record/wait — which are graph-capturable — happen per call).
    static cudaStream_t s_side = nullptr;
    static cudaEvent_t evFork = nullptr, evJoin = nullptr;
    if (s_side == nullptr) {
        cudaStreamCreateWithFlags(&s_side, cudaStreamNonBlocking);
        cudaEventCreateWithFlags(&evFork, cudaEventDisableTiming);
        cudaEventCreateWithFlags(&evJoin, cudaEventDisableTiming);
    }

    const int B = 256;
    int gNode = (nN + B - 1) / B;
    int gEdge = (nE + B - 1) / B;
    int gWarp = (nN + (B / 32) - 1) / (B / 32);
    int gGemm = 592;   // grid-stride, 4 blocks/SM

    k_init <<<gNode, B>>>(nN);
    k_deg  <<<gEdge, B>>>(src, dst, nE);
    k_norm <<<gNode, B>>>(nN);

    // fork: gemm runs on side stream concurrently with csr
    cudaEventRecord(evFork, 0);
    cudaStreamWaitEvent(s_side, evFork, 0);
    k_gemm <<<gGemm, B, 0, s_side>>>(feat, W1, nN);
    cudaEventRecord(evJoin, s_side);

    k_csr  <<<gEdge, B>>>(src, dst, nE);

    // join before pull1 (needs both esrc and y)
    cudaStreamWaitEvent(0, evJoin, 0);
    k_pull1<<<gWarp, B>>>(b1, W2, nN);
    k_pull2<<<gNode, B>>>(b2, out, nN);
}

// round 8
// speedup vs baseline: 1.3872x; 1.0456x over previous
#include <cuda_runtime.h>
#include <math.h>

#define NND 50000
#define NED 800000
#define D   64

// ---- scratch (allocation-free device globals) ----
__device__ int   g_degout[NND];
__device__ int   g_degin[NND];
__device__ float g_outn[NND];
__device__ float g_inn[NND];
__device__ int   g_rowstart[NND];
__device__ int   g_cursor[NND];
__device__ int   g_esrc[NED];      // edge src ids grouped by dst
__device__ float g_y[NND * D];     // feat @ W1  (NO out-norm; applied in pull1)
__device__ float g_z[NND];         // outn * dot(relu-layer output, W2)
__device__ int   g_total;

// ---------------------------------------------------------------- init
__global__ void k_init(int nN) {
    int i = blockIdx.x * blockDim.x + threadIdx.x;
    if (i < nN) { g_degout[i] = 0; g_degin[i] = 0; }
    if (i == 0) g_total = 0;
}

// ---------------------------------------------------------------- degrees
__global__ void k_deg(const int* __restrict__ src, const int* __restrict__ dst, int nE) {
    int e = blockIdx.x * blockDim.x + threadIdx.x;
    if (e < nE) {
        atomicAdd(&g_degout[src[e]], 1);
        atomicAdd(&g_degin[dst[e]], 1);
    }
}

// ---------------------------------------------------------------- norms + row offsets (warp-agg chunk grab)
__global__ void k_norm(int nN) {
    int i = blockIdx.x * blockDim.x + threadIdx.x;
    int lane = threadIdx.x & 31;
    int din = (i < nN) ? g_degin[i] : 0;

    int scan = din;
#pragma unroll
    for (int off = 1; off < 32; off <<= 1) {
        int u = __shfl_up_sync(0xffffffffu, scan, off);
        if (lane >= off) scan += u;
    }
    int wsum = __shfl_sync(0xffffffffu, scan, 31);
    int base = 0;
    if (lane == 31) base = atomicAdd(&g_total, wsum);
    base = __shfl_sync(0xffffffffu, base, 31);

    if (i < nN) {
        int rs = base + scan - din;
        g_rowstart[i] = rs;
        g_cursor[i]   = rs;
        g_outn[i] = rsqrtf(fmaxf((float)g_degout[i], 1.f));
        g_inn[i]  = rsqrtf(fmaxf((float)din, 1.f));
    }
}

// ---------------------------------------------------------------- CSR fill
__global__ void k_csr(const int* __restrict__ src, const int* __restrict__ dst, int nE) {
    int e = blockIdx.x * blockDim.x + threadIdx.x;
    if (e < nE) {
        int pos = atomicAdd(&g_cursor[dst[e]], 1);
        g_esrc[pos] = src[e];
    }
}

// ---------------------------------------------------------------- y = feat @ W1   (8 nodes per warp)
// Each LDS.64 of the W pair is amortized across 8 nodes (LDS traffic /8).
__global__ void k_gemm(const float* __restrict__ feat, const float* __restrict__ W1, int nN) {
    __shared__ float2 Ws[D * 32];   // Ws[k*32+l] = (W1[k][2l], W1[k][2l+1])
    int t = threadIdx.x;
    for (int i = t; i < D * 32; i += blockDim.x)
        Ws[i] = reinterpret_cast<const float2*>(W1)[i];
    __syncthreads();

    int lane = t & 31;
    int wid  = t >> 5;
    int gw   = blockIdx.x * (blockDim.x >> 5) + wid;   // global warp id
    int nb   = gw * 8;                                  // first node of this warp's group
    if (nb >= nN) return;

    if (nb + 8 <= nN) {
        float x0[8], x1[8], ax[8], ay[8];
#pragma unroll
        for (int n = 0; n < 8; n++) {
            x0[n] = feat[(nb + n) * D + lane];
            x1[n] = feat[(nb + n) * D + 32 + lane];
            ax[n] = 0.f; ay[n] = 0.f;
        }
#pragma unroll
        for (int k = 0; k < D; k++) {
            float2 w = Ws[k * 32 + lane];
#pragma unroll
            for (int n = 0; n < 8; n++) {
                float v = __shfl_sync(0xffffffffu, (k < 32) ? x0[n] : x1[n], k & 31);
                ax[n] = fmaf(v, w.x, ax[n]);
                ay[n] = fmaf(v, w.y, ay[n]);
            }
        }
#pragma unroll
        for (int n = 0; n < 8; n++) {
            float2 r; r.x = ax[n]; r.y = ay[n];
            reinterpret_cast<float2*>(g_y)[(nb + n) * 32 + lane] = r;
        }
    } else {
        for (int node = nb; node < nN; node++) {
            float x0 = feat[node * D + lane];
            float x1 = feat[node * D + 32 + lane];
            float ax = 0.f, ay = 0.f;
#pragma unroll
            for (int k = 0; k < D; k++) {
                float v = __shfl_sync(0xffffffffu, (k < 32) ? x0 : x1, k & 31);
                float2 w = Ws[k * 32 + lane];
                ax = fmaf(v, w.x, ax);
                ay = fmaf(v, w.y, ay);
            }
            float2 r; r.x = ax; r.y = ay;
            reinterpret_cast<float2*>(g_y)[node * 32 + lane] = r;
        }
    }
}

// ---------------------------------------------------------------- layer 1 pull + epilogue -> z
// outn applied per-source here (y carries no norm), freeing gemm from the degree pass.
__global__ void k_pull1(const float* __restrict__ b1, const float* __restrict__ W2, int nN) {
    int t = threadIdx.x;
    int lane = t & 31;
    int wid  = t >> 5;
    int warps = (blockDim.x >> 5) * gridDim.x;
    float2 b1v = reinterpret_cast<const float2*>(b1)[lane];
    float2 w2v = reinterpret_cast<const float2*>(W2)[lane];
    const float2* y2 = reinterpret_cast<const float2*>(g_y);

    for (int node = blockIdx.x * (blockDim.x >> 5) + wid; node < nN; node += warps) {
        int row = g_rowstart[node];
        int deg = g_degin[node];
        float ax = 0.f, ay = 0.f;
        for (int base = 0; base < deg; base += 32) {
            int n = min(32, deg - base);
            int eid = (lane < n) ? g_esrc[row + base + lane] : 0;
            for (int j = 0; j < n; j++) {
                int s = __shfl_sync(0xffffffffu, eid, j);
                float os = g_outn[s];             // uniform load, L1-resident
                float2 v = y2[s * 32 + lane];
                ax = fmaf(v.x, os, ax);
                ay = fmaf(v.y, os, ay);
            }
        }
        float inn = g_inn[node];
        float hx = fmaxf(fmaf(ax, inn, b1v.x), 0.f);
        float hy = fmaxf(fmaf(ay, inn, b1v.y), 0.f);
        float p = hx * w2v.x + hy * w2v.y;
#pragma unroll
        for (int o = 16; o; o >>= 1) p += __shfl_xor_sync(0xffffffffu, p, o);
        if (lane == 0) g_z[node] = p * g_outn[node];
    }
}

// ---------------------------------------------------------------- layer 2: scalar pull + sigmoid
__global__ void k_pull2(const float* __restrict__ b2, float* __restrict__ out, int nN) {
    int i = blockIdx.x * blockDim.x + threadIdx.x;
    if (i < nN) {
        int row = g_rowstart[i];
        int deg = g_degin[i];
        float s = 0.f;
        for (int e = 0; e < deg; e++) s += g_z[g_esrc[row + e]];
        out[i] = 1.f / (1.f + expf(-(s * g_inn[i] + b2[0])));
    }
}

// ---------------------------------------------------------------- launch
extern "C" void kernel_launch(void* const* d_in, const int* in_sizes, int n_in,
                              void* d_out, int out_size) {
    const float* feat = (const float*)d_in[0];
    const float* W1   = (const float*)d_in[1];
    const float* b1   = (const float*)d_in[2];
    const float* W2   = (const float*)d_in[3];
    const float* b2   = (const float*)d_in[4];
    const int*   src  = (const int*)d_in[5];
    const int*   dst  = (const int*)d_in[6];
    float* out = (float*)d_out;

    int nN = in_sizes[0] / D;
    int nE = in_sizes[5];

    static cudaStream_t s_side = nullptr;
    static cudaEvent_t evFork = nullptr, evJoin = nullptr;
    if (s_side == nullptr) {
        cudaStreamCreateWithFlags(&s_side, cudaStreamNonBlocking);
        cudaEventCreateWithFlags(&evFork, cudaEventDisableTiming);
        cudaEventCreateWithFlags(&evJoin, cudaEventDisableTiming);
    }

    const int B = 256;
    int gNode = (nN + B - 1) / B;
    int gEdge = (nE + B - 1) / B;
    int gWarp = (nN + (B / 32) - 1) / (B / 32);
    int gGemm = (nN + 8 * (B / 32) - 1) / (8 * (B / 32));   // 8 nodes/warp

    // fork gemm immediately — it depends only on feat/W1
    cudaEventRecord(evFork, 0);
    cudaStreamWaitEvent(s_side, evFork, 0);
    k_gemm <<<gGemm, B, 0, s_side>>>(feat, W1, nN);
    cudaEventRecord(evJoin, s_side);

    k_init <<<gNode, B>>>(nN);
    k_deg  <<<gEdge, B>>>(src, dst, nE);
    k_norm <<<gNode, B>>>(nN);
    k_csr  <<<gEdge, B>>>(src, dst, nE);

    cudaStreamWaitEvent(0, evJoin, 0);
    k_pull1<<<gWarp, B>>>(b1, W2, nN);
    k_pull2<<<gNode, B>>>(b2, out, nN);
}

// round 9
// speedup vs baseline: 1.3970x; 1.0070x over previous
#include <cuda_runtime.h>
#include <cuda_fp16.h>
#include <math.h>

#define NND 50000
#define NED 800000
#define D   64

// ---- scratch (allocation-free device globals) ----
__device__ int     g_degout[NND];
__device__ int     g_degin[NND];
__device__ float   g_outn[NND];
__device__ float   g_inn[NND];
__device__ int     g_rowstart[NND];
__device__ int     g_cursor[NND];
__device__ int     g_esrc[NED];       // edge src ids grouped by dst
__device__ __half2 g_yh[NND * 32];    // feat @ W1, fp16x2 (no out-norm; applied in pull1)
__device__ float   g_z[NND];          // outn * dot(relu-layer output, W2)
__device__ int     g_total;

// ================================================================ MAIN-STREAM CHAIN

// init: zero degin + total (degout zeroed on side stream)
__global__ void k_init_in(int nN) {
    int i = blockIdx.x * blockDim.x + threadIdx.x;
    if (i < nN) g_degin[i] = 0;
    if (i == 0) g_total = 0;
}

// in-degrees only
__global__ void k_deg_in(const int* __restrict__ dst, int nE) {
    int e = blockIdx.x * blockDim.x + threadIdx.x;
    if (e < nE) atomicAdd(&g_degin[dst[e]], 1);
}

// row offsets (warp-agg chunk grab) + inn
__global__ void k_norm(int nN) {
    int i = blockIdx.x * blockDim.x + threadIdx.x;
    int lane = threadIdx.x & 31;
    int din = (i < nN) ? g_degin[i] : 0;

    int scan = din;
#pragma unroll
    for (int off = 1; off < 32; off <<= 1) {
        int u = __shfl_up_sync(0xffffffffu, scan, off);
        if (lane >= off) scan += u;
    }
    int wsum = __shfl_sync(0xffffffffu, scan, 31);
    int base = 0;
    if (lane == 31) base = atomicAdd(&g_total, wsum);
    base = __shfl_sync(0xffffffffu, base, 31);

    if (i < nN) {
        int rs = base + scan - din;
        g_rowstart[i] = rs;
        g_cursor[i]   = rs;
        g_inn[i] = rsqrtf(fmaxf((float)din, 1.f));
    }
}

// CSR fill
__global__ void k_csr(const int* __restrict__ src, const int* __restrict__ dst, int nE) {
    int e = blockIdx.x * blockDim.x + threadIdx.x;
    if (e < nE) {
        int pos = atomicAdd(&g_cursor[dst[e]], 1);
        g_esrc[pos] = src[e];
    }
}

// ================================================================ SIDE-STREAM CHAIN

// y = feat @ W1, 8 nodes/warp, fp16 output
__global__ void k_gemm(const float* __restrict__ feat, const float* __restrict__ W1, int nN) {
    __shared__ float2 Ws[D * 32];   // Ws[k*32+l] = (W1[k][2l], W1[k][2l+1])
    int t = threadIdx.x;
    for (int i = t; i < D * 32; i += blockDim.x)
        Ws[i] = reinterpret_cast<const float2*>(W1)[i];
    __syncthreads();

    int lane = t & 31;
    int wid  = t >> 5;
    int gw   = blockIdx.x * (blockDim.x >> 5) + wid;
    int nb   = gw * 8;
    if (nb >= nN) return;

    if (nb + 8 <= nN) {
        float x0[8], x1[8], ax[8], ay[8];
#pragma unroll
        for (int n = 0; n < 8; n++) {
            x0[n] = feat[(nb + n) * D + lane];
            x1[n] = feat[(nb + n) * D + 32 + lane];
            ax[n] = 0.f; ay[n] = 0.f;
        }
#pragma unroll
        for (int k = 0; k < D; k++) {
            float2 w = Ws[k * 32 + lane];
#pragma unroll
            for (int n = 0; n < 8; n++) {
                float v = __shfl_sync(0xffffffffu, (k < 32) ? x0[n] : x1[n], k & 31);
                ax[n] = fmaf(v, w.x, ax[n]);
                ay[n] = fmaf(v, w.y, ay[n]);
            }
        }
#pragma unroll
        for (int n = 0; n < 8; n++)
            g_yh[(nb + n) * 32 + lane] = __floats2half2_rn(ax[n], ay[n]);
    } else {
        for (int node = nb; node < nN; node++) {
            float x0 = feat[node * D + lane];
            float x1 = feat[node * D + 32 + lane];
            float ax = 0.f, ay = 0.f;
#pragma unroll
            for (int k = 0; k < D; k++) {
                float v = __shfl_sync(0xffffffffu, (k < 32) ? x0 : x1, k & 31);
                float2 w = Ws[k * 32 + lane];
                ax = fmaf(v, w.x, ax);
                ay = fmaf(v, w.y, ay);
            }
            g_yh[node * 32 + lane] = __floats2half2_rn(ax, ay);
        }
    }
}

__global__ void k_init_out(int nN) {
    int i = blockIdx.x * blockDim.x + threadIdx.x;
    if (i < nN) g_degout[i] = 0;
}

__global__ void k_deg_out(const int* __restrict__ src, int nE) {
    int e = blockIdx.x * blockDim.x + threadIdx.x;
    if (e < nE) atomicAdd(&g_degout[src[e]], 1);
}

__global__ void k_outn(int nN) {
    int i = blockIdx.x * blockDim.x + threadIdx.x;
    if (i < nN) g_outn[i] = rsqrtf(fmaxf((float)g_degout[i], 1.f));
}

// ================================================================ JOINED TAIL

// layer 1 pull (fp16 gather) + outn-on-source + MLP epilogue -> z
__global__ void k_pull1(const float* __restrict__ b1, const float* __restrict__ W2, int nN) {
    int t = threadIdx.x;
    int lane = t & 31;
    int wid  = t >> 5;
    int warps = (blockDim.x >> 5) * gridDim.x;
    float2 b1v = reinterpret_cast<const float2*>(b1)[lane];
    float2 w2v = reinterpret_cast<const float2*>(W2)[lane];

    for (int node = blockIdx.x * (blockDim.x >> 5) + wid; node < nN; node += warps) {
        int row = g_rowstart[node];
        int deg = g_degin[node];
        float ax = 0.f, ay = 0.f;
        for (int base = 0; base < deg; base += 32) {
            int n = min(32, deg - base);
            int eid = (lane < n) ? g_esrc[row + base + lane] : 0;
            for (int j = 0; j < n; j++) {
                int s = __shfl_sync(0xffffffffu, eid, j);
                float os = g_outn[s];
                float2 v = __half22float2(g_yh[s * 32 + lane]);
                ax = fmaf(v.x, os, ax);
                ay = fmaf(v.y, os, ay);
            }
        }
        float inn = g_inn[node];
        float hx = fmaxf(fmaf(ax, inn, b1v.x), 0.f);
        float hy = fmaxf(fmaf(ay, inn, b1v.y), 0.f);
        float p = hx * w2v.x + hy * w2v.y;
#pragma unroll
        for (int o = 16; o; o >>= 1) p += __shfl_xor_sync(0xffffffffu, p, o);
        if (lane == 0) g_z[node] = p * g_outn[node];
    }
}

// layer 2: scalar pull + sigmoid
__global__ void k_pull2(const float* __restrict__ b2, float* __restrict__ out, int nN) {
    int i = blockIdx.x * blockDim.x + threadIdx.x;
    if (i < nN) {
        int row = g_rowstart[i];
        int deg = g_degin[i];
        float s = 0.f;
        for (int e = 0; e < deg; e++) s += g_z[g_esrc[row + e]];
        out[i] = 1.f / (1.f + expf(-(s * g_inn[i] + b2[0])));
    }
}

// ================================================================ launch
extern "C" void kernel_launch(void* const* d_in, const int* in_sizes, int n_in,
                              void* d_out, int out_size) {
    const float* feat = (const float*)d_in[0];
    const float* W1   = (const float*)d_in[1];
    const float* b1   = (const float*)d_in[2];
    const float* W2   = (const float*)d_in[3];
    const float* b2   = (const float*)d_in[4];
    const int*   src  = (const int*)d_in[5];
    const int*   dst  = (const int*)d_in[6];
    float* out = (float*)d_out;

    int nN = in_sizes[0] / D;
    int nE = in_sizes[5];

    static cudaStream_t s_side = nullptr;
    static cudaEvent_t evFork = nullptr, evJoin = nullptr;
    if (s_side == nullptr) {
        cudaStreamCreateWithFlags(&s_side, cudaStreamNonBlocking);
        cudaEventCreateWithFlags(&evFork, cudaEventDisableTiming);
        cudaEventCreateWithFlags(&evJoin, cudaEventDisableTiming);
    }

    const int B = 256;
    int gNode = (nN + B - 1) / B;
    int gEdge = (nE + B - 1) / B;
    int gWarp = (nN + (B / 32) - 1) / (B / 32);
    int gGemm = (nN + 8 * (B / 32) - 1) / (8 * (B / 32));

    // side chain: gemm -> degout -> outn   (independent of degin/csr)
    cudaEventRecord(evFork, 0);
    cudaStreamWaitEvent(s_side, evFork, 0);
    k_gemm    <<<gGemm, B, 0, s_side>>>(feat, W1, nN);
    k_init_out<<<gNode, B, 0, s_side>>>(nN);
    k_deg_out <<<gEdge, B, 0, s_side>>>(src, nE);
    k_outn    <<<gNode, B, 0, s_side>>>(nN);
    cudaEventRecord(evJoin, s_side);

    // main chain: degin -> norm -> csr
    k_init_in<<<gNode, B>>>(nN);
    k_deg_in <<<gEdge, B>>>(dst, nE);
    k_norm   <<<gNode, B>>>(nN);
    k_csr    <<<gEdge, B>>>(src, dst, nE);

    cudaStreamWaitEvent(0, evJoin, 0);
    k_pull1<<<gWarp, B>>>(b1, W2, nN);
    k_pull2<<<gNode, B>>>(b2, out, nN);
}

// round 10
// speedup vs baseline: 1.4355x; 1.0276x over previous
#include <cuda_runtime.h>
#include <cuda_fp16.h>
#include <math.h>

#define NND 50000
#define NED 800000
#define D   64

// ---- scratch (allocation-free device globals) ----
__device__ int     g_degout[NND];
__device__ int     g_degin[NND];
__device__ float   g_outn[NND];
__device__ float   g_inn[NND];
__device__ int     g_rowstart[NND];
__device__ int     g_cursor[NND];
__device__ int     g_esrc[NED];       // edge src ids grouped by dst
__device__ __half2 g_yh[NND * 32];    // feat @ W1, fp16x2 (no out-norm; applied in pull1)
__device__ float   g_z[NND];          // outn * dot(relu-layer output, W2)
__device__ int     g_total;

// ================================================================ MAIN-STREAM CHAIN

__global__ void k_init_in(int nN) {
    int i = blockIdx.x * blockDim.x + threadIdx.x;
    if (i < nN) g_degin[i] = 0;
    if (i == 0) g_total = 0;
}

__global__ void k_deg_in(const int* __restrict__ dst, int nE) {
    int e = blockIdx.x * blockDim.x + threadIdx.x;
    if (e < nE) atomicAdd(&g_degin[dst[e]], 1);
}

__global__ void k_norm(int nN) {
    int i = blockIdx.x * blockDim.x + threadIdx.x;
    int lane = threadIdx.x & 31;
    int din = (i < nN) ? g_degin[i] : 0;

    int scan = din;
#pragma unroll
    for (int off = 1; off < 32; off <<= 1) {
        int u = __shfl_up_sync(0xffffffffu, scan, off);
        if (lane >= off) scan += u;
    }
    int wsum = __shfl_sync(0xffffffffu, scan, 31);
    int base = 0;
    if (lane == 31) base = atomicAdd(&g_total, wsum);
    base = __shfl_sync(0xffffffffu, base, 31);

    if (i < nN) {
        int rs = base + scan - din;
        g_rowstart[i] = rs;
        g_cursor[i]   = rs;
        g_inn[i] = rsqrtf(fmaxf((float)din, 1.f));
    }
}

__global__ void k_csr(const int* __restrict__ src, const int* __restrict__ dst, int nE) {
    int e = blockIdx.x * blockDim.x + threadIdx.x;
    if (e < nE) {
        int pos = atomicAdd(&g_cursor[dst[e]], 1);
        g_esrc[pos] = src[e];
    }
}

// ================================================================ SIDE-STREAM CHAIN

__global__ void k_gemm(const float* __restrict__ feat, const float* __restrict__ W1, int nN) {
    __shared__ float2 Ws[D * 32];
    int t = threadIdx.x;
    for (int i = t; i < D * 32; i += blockDim.x)
        Ws[i] = reinterpret_cast<const float2*>(W1)[i];
    __syncthreads();

    int lane = t & 31;
    int wid  = t >> 5;
    int gw   = blockIdx.x * (blockDim.x >> 5) + wid;
    int nb   = gw * 8;
    if (nb >= nN) return;

    if (nb + 8 <= nN) {
        float x0[8], x1[8], ax[8], ay[8];
#pragma unroll
        for (int n = 0; n < 8; n++) {
            x0[n] = feat[(nb + n) * D + lane];
            x1[n] = feat[(nb + n) * D + 32 + lane];
            ax[n] = 0.f; ay[n] = 0.f;
        }
#pragma unroll
        for (int k = 0; k < D; k++) {
            float2 w = Ws[k * 32 + lane];
#pragma unroll
            for (int n = 0; n < 8; n++) {
                float v = __shfl_sync(0xffffffffu, (k < 32) ? x0[n] : x1[n], k & 31);
                ax[n] = fmaf(v, w.x, ax[n]);
                ay[n] = fmaf(v, w.y, ay[n]);
            }
        }
#pragma unroll
        for (int n = 0; n < 8; n++)
            g_yh[(nb + n) * 32 + lane] = __floats2half2_rn(ax[n], ay[n]);
    } else {
        for (int node = nb; node < nN; node++) {
            float x0 = feat[node * D + lane];
            float x1 = feat[node * D + 32 + lane];
            float ax = 0.f, ay = 0.f;
#pragma unroll
            for (int k = 0; k < D; k++) {
                float v = __shfl_sync(0xffffffffu, (k < 32) ? x0 : x1, k & 31);
                float2 w = Ws[k * 32 + lane];
                ax = fmaf(v, w.x, ax);
                ay = fmaf(v, w.y, ay);
            }
            g_yh[node * 32 + lane] = __floats2half2_rn(ax, ay);
        }
    }
}

__global__ void k_init_out(int nN) {
    int i = blockIdx.x * blockDim.x + threadIdx.x;
    if (i < nN) g_degout[i] = 0;
}

__global__ void k_deg_out(const int* __restrict__ src, int nE) {
    int e = blockIdx.x * blockDim.x + threadIdx.x;
    if (e < nE) atomicAdd(&g_degout[src[e]], 1);
}

__global__ void k_outn(int nN) {
    int i = blockIdx.x * blockDim.x + threadIdx.x;
    if (i < nN) g_outn[i] = rsqrtf(fmaxf((float)g_degout[i], 1.f));
}

// ================================================================ JOINED TAIL

// layer 1 pull: software-pipelined 8-edge groups (16 independent loads in flight)
__global__ void k_pull1(const float* __restrict__ b1, const float* __restrict__ W2, int nN) {
    int t = threadIdx.x;
    int lane = t & 31;
    int wid  = t >> 5;
    int warps = (blockDim.x >> 5) * gridDim.x;
    float2 b1v = reinterpret_cast<const float2*>(b1)[lane];
    float2 w2v = reinterpret_cast<const float2*>(W2)[lane];

    for (int node = blockIdx.x * (blockDim.x >> 5) + wid; node < nN; node += warps) {
        int row = g_rowstart[node];
        int deg = g_degin[node];
        float ax = 0.f, ay = 0.f;
        for (int base = 0; base < deg; base += 32) {
            int n = min(32, deg - base);
            int eid = (lane < n) ? g_esrc[row + base + lane] : 0;
            int j = 0;
            for (; j + 8 <= n; j += 8) {
                int s[8];
#pragma unroll
                for (int g = 0; g < 8; g++) s[g] = __shfl_sync(0xffffffffu, eid, j + g);
                __half2 vh[8];
                float os[8];
#pragma unroll
                for (int g = 0; g < 8; g++) { vh[g] = g_yh[s[g] * 32 + lane]; os[g] = g_outn[s[g]]; }
#pragma unroll
                for (int g = 0; g < 8; g++) {
                    float2 v = __half22float2(vh[g]);
                    ax = fmaf(v.x, os[g], ax);
                    ay = fmaf(v.y, os[g], ay);
                }
            }
            for (; j < n; j++) {
                int s = __shfl_sync(0xffffffffu, eid, j);
                float os = g_outn[s];
                float2 v = __half22float2(g_yh[s * 32 + lane]);
                ax = fmaf(v.x, os, ax);
                ay = fmaf(v.y, os, ay);
            }
        }
        float inn = g_inn[node];
        float hx = fmaxf(fmaf(ax, inn, b1v.x), 0.f);
        float hy = fmaxf(fmaf(ay, inn, b1v.y), 0.f);
        float p = hx * w2v.x + hy * w2v.y;
#pragma unroll
        for (int o = 16; o; o >>= 1) p += __shfl_xor_sync(0xffffffffu, p, o);
        if (lane == 0) g_z[node] = p * g_outn[node];
    }
}

// layer 2: scalar pull, 8 independent accumulators
__global__ void k_pull2(const float* __restrict__ b2, float* __restrict__ out, int nN) {
    int i = blockIdx.x * blockDim.x + threadIdx.x;
    if (i >= nN) return;
    int row = g_rowstart[i];
    int deg = g_degin[i];
    float a[8];
#pragma unroll
    for (int g = 0; g < 8; g++) a[g] = 0.f;
    int e = 0;
    for (; e + 8 <= deg; e += 8) {
        int sv[8];
#pragma unroll
        for (int g = 0; g < 8; g++) sv[g] = g_esrc[row + e + g];
#pragma unroll
        for (int g = 0; g < 8; g++) a[g] += g_z[sv[g]];
    }
    for (; e < deg; e++) a[0] += g_z[g_esrc[row + e]];
    float s = ((a[0] + a[1]) + (a[2] + a[3])) + ((a[4] + a[5]) + (a[6] + a[7]));
    out[i] = 1.f / (1.f + expf(-(s * g_inn[i] + b2[0])));
}

// ================================================================ launch
extern "C" void kernel_launch(void* const* d_in, const int* in_sizes, int n_in,
                              void* d_out, int out_size) {
    const float* feat = (const float*)d_in[0];
    const float* W1   = (const float*)d_in[1];
    const float* b1   = (const float*)d_in[2];
    const float* W2   = (const float*)d_in[3];
    const float* b2   = (const float*)d_in[4];
    const int*   src  = (const int*)d_in[5];
    const int*   dst  = (const int*)d_in[6];
    float* out = (float*)d_out;

    int nN = in_sizes[0] / D;
    int nE = in_sizes[5];

    static cudaStream_t s_side = nullptr;
    static cudaEvent_t evFork = nullptr, evJoin = nullptr;
    if (s_side == nullptr) {
        cudaStreamCreateWithFlags(&s_side, cudaStreamNonBlocking);
        cudaEventCreateWithFlags(&evFork, cudaEventDisableTiming);
        cudaEventCreateWithFlags(&evJoin, cudaEventDisableTiming);
    }

    const int B = 256;
    int gNode = (nN + B - 1) / B;
    int gEdge = (nE + B - 1) / B;
    int gWarp = (nN + (B / 32) - 1) / (B / 32);
    int gGemm = (nN + 8 * (B / 32) - 1) / (8 * (B / 32));

    // side chain: gemm -> degout -> outn
    cudaEventRecord(evFork, 0);
    cudaStreamWaitEvent(s_side, evFork, 0);
    k_gemm    <<<gGemm, B, 0, s_side>>>(feat, W1, nN);
    k_init_out<<<gNode, B, 0, s_side>>>(nN);
    k_deg_out <<<gEdge, B, 0, s_side>>>(src, nE);
    k_outn    <<<gNode, B, 0, s_side>>>(nN);
    cudaEventRecord(evJoin, s_side);

    // main chain: degin -> norm -> csr
    k_init_in<<<gNode, B>>>(nN);
    k_deg_in <<<gEdge, B>>>(dst, nE);
    k_norm   <<<gNode, B>>>(nN);
    k_csr    <<<gEdge, B>>>(src, dst, nE);

    cudaStreamWaitEvent(0, evJoin, 0);
    k_pull1<<<gWarp, B>>>(b1, W2, nN);
    k_pull2<<<gNode, B>>>(b2, out, nN);
}